// round 9
// baseline (speedup 1.0000x reference)
#include <cuda_runtime.h>
#include <cuda_bf16.h>

// Problem constants
#define Hc 200          // H
#define Wc 196          // W
#define NPIX (Hc * Wc)  // 39200 pixels per camera
#define NCH 256
#define NCAM 6
#define SSZ 400
#define NCELL (SSZ * SSZ)    // 160000

// Scratch (allocation-free rule). Zero at module load; finalize re-zeros after
// reading, so the grids are zero at every kernel_launch entry (correctness run
// and every graph replay).
__device__ float g_sum[NCELL];
__device__ float g_cnt[NCELL];

// One thread per (cam, pixel), scalar LDG.32 streaming (measured fastest
// per-byte across R2..R5: scalar 5.6 TB/s vs float4 5.2 TB/s). pix = w*H + h
// is the memory-contiguous index; channel loop strides NPIX -> each warp
// instruction fetches exactly one 128B line (1 L1tex wavefront, cross-LDG
// rate). 128-thread blocks: 1842 blocks, single wave, ~5% tail quantization.
// Mask read as 32-bit word: correct for int32 AND float32 bool storage
// (true nonzero in both); u8 storage ruled out empirically in R1.
__global__ __launch_bounds__(128) void bev_dot_scatter_kernel(
    const float* __restrict__ feats,   // [NCAM, NCH, Wc, Hc]
    const float* __restrict__ mats,    // [NCAM, 4, 4]
    const float* __restrict__ lc,      // [4, NPIX], n = h*W + w
    const int*   __restrict__ mask,    // [NPIX]
    const float* __restrict__ w_cls)   // [NCH]
{
    __shared__ float sw[NCH];
    __shared__ float sm[8];  // rows 0,1 of this cam's 4x4

    const int tid = threadIdx.x;
    const int cam = blockIdx.y;

    sw[tid]       = w_cls[tid];
    sw[tid + 128] = w_cls[tid + 128];
    if (tid < 8) sm[tid] = mats[cam * 16 + tid];
    __syncthreads();

    const int pix = blockIdx.x * 128 + tid;
    if (pix >= NPIX) return;

    // pix = w*H + h ; logical flat index n = h*W + w
    const int wq = pix / Hc;
    const int h  = pix - wq * Hc;
    const int n  = h * Wc + wq;

    // Early out: masked pixels contribute nothing — skip the 256-load loop.
    if (mask[n] == 0) return;

    const float* p = feats + (size_t)cam * NCH * NPIX + pix;

    float a0 = 0.f, a1 = 0.f, a2 = 0.f, a3 = 0.f;
#pragma unroll 8
    for (int ch = 0; ch < NCH; ch += 4) {
        a0 = fmaf(p[(ch + 0) * NPIX], sw[ch + 0], a0);
        a1 = fmaf(p[(ch + 1) * NPIX], sw[ch + 1], a1);
        a2 = fmaf(p[(ch + 2) * NPIX], sw[ch + 2], a2);
        a3 = fmaf(p[(ch + 3) * NPIX], sw[ch + 3], a3);
    }
    const float dot = (a0 + a1) + (a2 + a3);

    const float gx = lc[n];
    const float gy = lc[NPIX + n];
    const float x = sm[0] * gx + sm[1] * gy + sm[3];
    const float y = sm[4] * gx + sm[5] * gy + sm[7];
    // (coord + 100) / 0.5 == (coord + 100) * 2 exactly; jnp.round == rintf
    const float fx = rintf((x + 100.0f) * 2.0f);
    const float fy = rintf((y + 100.0f) * 2.0f);
    if (fx >= 0.0f && fx < (float)SSZ && fy >= 0.0f && fy < (float)SSZ) {
        const int cell = (int)fx * SSZ + (int)fy;
        atomicAdd(&g_sum[cell], dot);
        atomicAdd(&g_cnt[cell], 1.0f);
    }
}

// Finalize AND restore scratch to zero for the next run (graph replay invariant).
__global__ __launch_bounds__(128) void finalize_kernel(float* __restrict__ out,
                                                       const float* __restrict__ b_cls) {
    int i4 = blockIdx.x * 128 + threadIdx.x;
    if (i4 >= NCELL / 4) return;
    float4* s4 = (float4*)g_sum + i4;
    float4* c4 = (float4*)g_cnt + i4;
    float4 s = *s4;
    float4 c = *c4;
    const float b = b_cls[0];
    float4 o;
    // where(cnt>=1, sum/max(cnt,1), sum) == sum/max(cnt,1): sum==0 when cnt==0
    o.x = s.x / fmaxf(c.x, 1.0f) + b;
    o.y = s.y / fmaxf(c.y, 1.0f) + b;
    o.z = s.z / fmaxf(c.z, 1.0f) + b;
    o.w = s.w / fmaxf(c.w, 1.0f) + b;
    ((float4*)out)[i4] = o;
    float4 z = make_float4(0.f, 0.f, 0.f, 0.f);
    *s4 = z;
    *c4 = z;
}

extern "C" void kernel_launch(void* const* d_in, const int* in_sizes, int n_in,
                              void* d_out, int out_size) {
    // Resolve inputs by element count (all distinct) — robust to metadata order.
    const float* feats = 0; const float* mats = 0; const float* lc = 0;
    const int*   mask  = 0; const float* w_cls = 0; const float* b_cls = 0;
    for (int i = 0; i < n_in; i++) {
        switch (in_sizes[i]) {
            case 60211200: feats = (const float*)d_in[i]; break;
            case 96:       mats  = (const float*)d_in[i]; break;
            case 156800:   lc    = (const float*)d_in[i]; break;
            case 39200:    mask  = (const int*)d_in[i];   break;
            case 256:      w_cls = (const float*)d_in[i]; break;
            case 1:        b_cls = (const float*)d_in[i]; break;
        }
    }
    float* out = (float*)d_out;

    dim3 grid((NPIX + 127) / 128, NCAM);   // 307 x 6 = 1842 blocks, one wave
    bev_dot_scatter_kernel<<<grid, 128>>>(feats, mats, lc, mask, w_cls);

    finalize_kernel<<<(NCELL / 4 + 127) / 128, 128>>>(out, b_cls);
}